// round 3
// baseline (speedup 1.0000x reference)
#include <cuda_runtime.h>

#define FIN 128
#define HH  128
#define C3  384
#define MAXN 50000
#define MAXE 800000
#define BM 128
#define BN 128
#define BK 8

// ---------------- static device scratch (allocation-free rule) ----------------
__device__ float d_XW[(size_t)MAXN * C3];     // [hgat | hgcn | x@W_sage_r]
__device__ float d_h[(size_t)MAXN * C3];      // concat features
__device__ float d_meanb[(size_t)MAXN * HH];  // SAGE neighbor mean
__device__ float d_z1[(size_t)MAXN * 256];
__device__ float d_z2[(size_t)MAXN * 128];
__device__ float d_as[MAXN], d_ad[MAXN], d_dinv[MAXN];
__device__ int   d_deg[MAXN];
__device__ int   d_rowptr[MAXN + 1];
__device__ int   d_cursor[MAXN];
__device__ int   d_srclist[MAXE];
__device__ float d_Wpack[FIN * C3];
__device__ float d_sum[C3], d_sumsq[C3], d_bns[C3], d_bnt[C3];
__device__ int   d_is32;   // 1 if edge_index is int32 on device, 0 if int64

// Tags for resolving internal scratch pointers inside device code
#define TAG_EXT     (-1)
#define TAG_XW      0
#define TAG_XW256   1
#define TAG_H       2
#define TAG_H256    3
#define TAG_MEANB   4
#define TAG_Z1      5
#define TAG_Z2      6
#define TAG_WPACK   7
#define TAG_BNS     8
#define TAG_BNT     9

__device__ __forceinline__ const float* resolve_c(int tag, const float* ext) {
    switch (tag) {
        case TAG_XW:    return d_XW;
        case TAG_XW256: return d_XW + 256;
        case TAG_H:     return d_h;
        case TAG_H256:  return d_h + 256;
        case TAG_MEANB: return d_meanb;
        case TAG_Z1:    return d_z1;
        case TAG_Z2:    return d_z2;
        case TAG_WPACK: return d_Wpack;
        case TAG_BNS:   return d_bns;
        case TAG_BNT:   return d_bnt;
        default:        return ext;
    }
}
__device__ __forceinline__ float* resolve_m(int tag, float* ext) {
    switch (tag) {
        case TAG_XW:    return d_XW;
        case TAG_XW256: return d_XW + 256;
        case TAG_H:     return d_h;
        case TAG_H256:  return d_h + 256;
        case TAG_MEANB: return d_meanb;
        case TAG_Z1:    return d_z1;
        case TAG_Z2:    return d_z2;
        default:        return ext;
    }
}

// ---------------- edge dtype detection + safe accessor ----------------
// If the harness materialized int64 edge_index as int32, interpreting the
// buffer as int64 yields garbage (two fused ids). Sample under the int64
// interpretation; any out-of-range value => int32. Sampled indices kept < E
// so the byte range is valid under BOTH interpretations.
__global__ void detect_kernel(const void* ei, int E, int n) {
    const long long* p64 = (const long long*)ei;
    int ok64 = 1;
    for (int i = 0; i < 16; i++) {
        size_t idx = ((size_t)i * 2654435761u) % (size_t)E;
        long long v = p64[idx];
        if (v < 0 || v >= (long long)n) { ok64 = 0; break; }
    }
    d_is32 = ok64 ? 0 : 1;
}

__device__ __forceinline__ int edge_get(const void* ei, size_t i, int n) {
    long long v = d_is32 ? (long long)((const int*)ei)[i]
                         : ((const long long*)ei)[i];
    if (v < 0) v = 0;
    if (v >= n) v = n - 1;
    return (int)v;
}

// ---------------- small kernels ----------------
__global__ void init_kernel(int n) {
    int i = blockIdx.x * blockDim.x + threadIdx.x;
    if (i < n) d_deg[i] = 0;
    if (i < C3) { d_sum[i] = 0.f; d_sumsq[i] = 0.f; }
}

__global__ void pack_w_kernel(const float* __restrict__ Wg,
                              const float* __restrict__ Wc,
                              const float* __restrict__ Wr) {
    int i = blockIdx.x * blockDim.x + threadIdx.x;
    if (i < FIN * HH) {
        int k = i >> 7, j = i & 127;
        d_Wpack[k * C3 + j]       = Wg[i];
        d_Wpack[k * C3 + 128 + j] = Wc[i];
        d_Wpack[k * C3 + 256 + j] = Wr[i];
    }
}

__global__ void count_deg_kernel(const void* __restrict__ ei, int E, int n) {
    int e = blockIdx.x * blockDim.x + threadIdx.x;
    if (e < E) atomicAdd(&d_deg[edge_get(ei, (size_t)E + e, n)], 1);
}

// single-block exclusive scan over deg -> rowptr, cursor; also dinv
__global__ void scan_kernel(int n) {
    __shared__ int sh[1024];
    int t = threadIdx.x;
    int chunk = (n + 1023) >> 10;
    int st = t * chunk, en = min(st + chunk, n);
    int s = 0;
    for (int i = st; i < en; i++) s += d_deg[i];
    sh[t] = s;
    __syncthreads();
    for (int off = 1; off < 1024; off <<= 1) {
        int add = (t >= off) ? sh[t - off] : 0;
        __syncthreads();
        sh[t] += add;
        __syncthreads();
    }
    int run = (t == 0) ? 0 : sh[t - 1];
    for (int i = st; i < en; i++) {
        d_rowptr[i] = run;
        d_cursor[i] = run;
        d_dinv[i] = rsqrtf((float)d_deg[i] + 1.0f);  // +1 self loop (GCN)
        run += d_deg[i];
    }
    if (t == 0) d_rowptr[n] = sh[1023];
}

__global__ void scatter_kernel(const void* __restrict__ ei, int E, int n) {
    int e = blockIdx.x * blockDim.x + threadIdx.x;
    if (e < E) {
        int s = edge_get(ei, (size_t)e, n);
        int d = edge_get(ei, (size_t)E + e, n);
        int pos = atomicAdd(&d_cursor[d], 1);
        if (pos >= 0 && pos < MAXE) d_srclist[pos] = s;
    }
}

// a_s = h_gat @ att_src, a_d = h_gat @ att_dst ; one warp per node
__global__ void asad_kernel(const float* __restrict__ att_src,
                            const float* __restrict__ att_dst, int n) {
    int w = (blockIdx.x * blockDim.x + threadIdx.x) >> 5;
    int lane = threadIdx.x & 31;
    if (w >= n) return;
    float4 h4 = ((const float4*)(d_XW + (size_t)w * C3))[lane];
    float4 s4 = ((const float4*)att_src)[lane];
    float4 t4 = ((const float4*)att_dst)[lane];
    float ss = h4.x * s4.x + h4.y * s4.y + h4.z * s4.z + h4.w * s4.w;
    float sd = h4.x * t4.x + h4.y * t4.y + h4.z * t4.z + h4.w * t4.w;
    #pragma unroll
    for (int off = 16; off > 0; off >>= 1) {
        ss += __shfl_down_sync(0xffffffffu, ss, off);
        sd += __shfl_down_sync(0xffffffffu, sd, off);
    }
    if (lane == 0) { d_as[w] = ss; d_ad[w] = sd; }
}

__device__ __forceinline__ float lrelu02(float e) { return e > 0.f ? e : 0.2f * e; }

// warp per dst node: fused GAT + GCN + SAGE aggregation (register accumulators)
__global__ void gather_kernel(const float* __restrict__ x,
                              const float* __restrict__ b_gat,
                              const float* __restrict__ b_gcn, int n) {
    int node = (blockIdx.x * blockDim.x + threadIdx.x) >> 5;
    int lane = threadIdx.x & 31;
    if (node >= n) return;
    int beg = d_rowptr[node], end = d_rowptr[node + 1];
    float adi = d_ad[node];
    float dvi = d_dinv[node];

    float4 gat = make_float4(0, 0, 0, 0);
    float4 gcn = make_float4(0, 0, 0, 0);
    float4 sg  = make_float4(0, 0, 0, 0);
    float den = 0.f;

    // self loop (GAT + GCN)
    {
        float w = __expf(lrelu02(d_as[node] + adi));
        den += w;
        const float4* base = (const float4*)(d_XW + (size_t)node * C3);
        float4 hg = base[lane];
        float4 hc = base[32 + lane];
        float nn = dvi * dvi;
        gat.x += w * hg.x; gat.y += w * hg.y; gat.z += w * hg.z; gat.w += w * hg.w;
        gcn.x += nn * hc.x; gcn.y += nn * hc.y; gcn.z += nn * hc.z; gcn.w += nn * hc.w;
    }

    for (int j0 = beg; j0 < end; j0 += 32) {
        int myj = j0 + lane;
        int s = 0; float w = 0.f, nrm = 0.f;
        if (myj < end) {
            s = d_srclist[myj];
            w = __expf(lrelu02(d_as[s] + adi));
            nrm = d_dinv[s] * dvi;
        }
        int cnt = min(32, end - j0);
        for (int q = 0; q < cnt; q++) {
            int   ss = __shfl_sync(0xffffffffu, s, q);
            float wq = __shfl_sync(0xffffffffu, w, q);
            float nq = __shfl_sync(0xffffffffu, nrm, q);
            const float4* base = (const float4*)(d_XW + (size_t)ss * C3);
            float4 hg = base[lane];
            float4 hc = base[32 + lane];
            float4 xv = ((const float4*)(x + (size_t)ss * FIN))[lane];
            gat.x += wq * hg.x; gat.y += wq * hg.y; gat.z += wq * hg.z; gat.w += wq * hg.w;
            gcn.x += nq * hc.x; gcn.y += nq * hc.y; gcn.z += nq * hc.z; gcn.w += nq * hc.w;
            sg.x += xv.x; sg.y += xv.y; sg.z += xv.z; sg.w += xv.w;
            den += wq;
        }
    }

    float invden = 1.0f / den;
    float invcnt = 1.0f / fmaxf((float)(end - beg), 1.0f);
    float4 bg = ((const float4*)b_gat)[lane];
    float4 bc = ((const float4*)b_gcn)[lane];
    float4 og = make_float4(gat.x * invden + bg.x, gat.y * invden + bg.y,
                            gat.z * invden + bg.z, gat.w * invden + bg.w);
    float4 oc = make_float4(gcn.x + bc.x, gcn.y + bc.y, gcn.z + bc.z, gcn.w + bc.w);
    float4 om = make_float4(sg.x * invcnt, sg.y * invcnt, sg.z * invcnt, sg.w * invcnt);
    ((float4*)(d_h + (size_t)node * C3))[lane] = og;
    ((float4*)(d_h + (size_t)node * C3 + 128))[lane] = oc;
    ((float4*)(d_meanb + (size_t)node * HH))[lane] = om;
}

// BN statistics
__global__ void bn_stats_kernel(int n) {
    int c = threadIdx.x;  // 384 threads
    float s = 0.f, s2 = 0.f;
    for (int r = blockIdx.x; r < n; r += gridDim.x) {
        float v = d_h[(size_t)r * C3 + c];
        s += v; s2 += v * v;
    }
    atomicAdd(&d_sum[c], s);
    atomicAdd(&d_sumsq[c], s2);
}

__global__ void bn_final_kernel(const float* __restrict__ gamma,
                                const float* __restrict__ beta, int n) {
    int c = threadIdx.x;
    if (c < C3) {
        float invn = 1.0f / (float)n;
        float mu = d_sum[c] * invn;
        float var = d_sumsq[c] * invn - mu * mu;
        float r = rsqrtf(var + 1e-5f);
        d_bns[c] = r * gamma[c];
        d_bnt[c] = beta[c] - mu * r * gamma[c];
    }
}

// ---------------- generic tiled fp32 GEMM: C = op(A) @ B [+bias] [+addv] ----------------
__global__ void __launch_bounds__(256)
gemm_kernel(int aTag, const float* aExt, int lda,
            int bTag, const float* bExt, int ldb,
            int cTag, float* cExt, int ldc,
            int M, int K, int Ncol,
            const float* __restrict__ bias,
            int addTag, int ldadd,
            int scaleTag, int shiftTag, int reluA) {
    const float* __restrict__ A = resolve_c(aTag, aExt);
    const float* __restrict__ B = resolve_c(bTag, bExt);
    float* __restrict__ C = resolve_m(cTag, cExt);
    const float* __restrict__ addv   = (addTag   == TAG_EXT) ? nullptr : resolve_c(addTag, nullptr);
    const float* __restrict__ ascale = (scaleTag == TAG_EXT) ? nullptr : resolve_c(scaleTag, nullptr);
    const float* __restrict__ ashift = (shiftTag == TAG_EXT) ? nullptr : resolve_c(shiftTag, nullptr);

    __shared__ float As[BK][BM];
    __shared__ float Bs[BK][BN];
    int tid = threadIdx.x;
    int tx = tid & 15, ty = tid >> 4;
    int row0 = blockIdx.y * BM, col0 = blockIdx.x * BN;
    float acc[8][8];
    #pragma unroll
    for (int i = 0; i < 8; i++)
        #pragma unroll
        for (int j = 0; j < 8; j++) acc[i][j] = 0.f;

    int arow = tid >> 1;
    int akb  = (tid & 1) * 4;
    int brow = tid >> 5;
    int bcol = (tid & 31) * 4;

    for (int k0 = 0; k0 < K; k0 += BK) {
        int grow = row0 + arow;
        #pragma unroll
        for (int j = 0; j < 4; j++) {
            int gk = k0 + akb + j;
            float a = 0.f;
            if (grow < M) {
                a = A[(size_t)grow * lda + gk];
                if (ascale) a = a * ascale[gk] + ashift[gk];
                if (reluA) a = fmaxf(a, 0.f);
            }
            As[akb + j][arow] = a;
        }
        #pragma unroll
        for (int j = 0; j < 4; j++) {
            int gc = col0 + bcol + j;
            float b = 0.f;
            if (gc < Ncol) b = B[(size_t)(k0 + brow) * ldb + gc];
            Bs[brow][bcol + j] = b;
        }
        __syncthreads();
        #pragma unroll
        for (int k = 0; k < BK; k++) {
            float av[8], bv[8];
            #pragma unroll
            for (int i = 0; i < 8; i++) av[i] = As[k][ty * 8 + i];
            #pragma unroll
            for (int j = 0; j < 8; j++) bv[j] = Bs[k][tx * 8 + j];
            #pragma unroll
            for (int i = 0; i < 8; i++)
                #pragma unroll
                for (int j = 0; j < 8; j++) acc[i][j] += av[i] * bv[j];
        }
        __syncthreads();
    }

    #pragma unroll
    for (int i = 0; i < 8; i++) {
        int r = row0 + ty * 8 + i;
        if (r >= M) continue;
        #pragma unroll
        for (int j = 0; j < 8; j++) {
            int c = col0 + tx * 8 + j;
            if (c >= Ncol) continue;
            float v = acc[i][j];
            if (bias) v += bias[c];
            if (addv) v += addv[(size_t)r * ldadd + c];
            C[(size_t)r * ldc + c] = v;
        }
    }
}

static void launch_gemm(int aTag, const float* aExt, int lda,
                        int bTag, const float* bExt, int ldb,
                        int cTag, float* cExt, int ldc,
                        int M, int K, int Ncol,
                        const float* bias,
                        int addTag, int ldadd,
                        int scaleTag, int shiftTag, int reluA) {
    dim3 g((Ncol + BN - 1) / BN, (M + BM - 1) / BM);
    gemm_kernel<<<g, 256>>>(aTag, aExt, lda, bTag, bExt, ldb, cTag, cExt, ldc,
                            M, K, Ncol, bias, addTag, ldadd,
                            scaleTag, shiftTag, reluA);
}

// ---------------- launch ----------------
extern "C" void kernel_launch(void* const* d_in, const int* in_sizes, int n_in,
                              void* d_out, int out_size) {
    const float* x        = (const float*)d_in[0];
    const void*  ei       = d_in[1];
    const float* W_gat    = (const float*)d_in[2];
    const float* att_src  = (const float*)d_in[3];
    const float* att_dst  = (const float*)d_in[4];
    const float* b_gat    = (const float*)d_in[5];
    const float* W_gcn    = (const float*)d_in[6];
    const float* b_gcn    = (const float*)d_in[7];
    const float* W_sage_l = (const float*)d_in[8];
    const float* b_sage_l = (const float*)d_in[9];
    const float* W_sage_r = (const float*)d_in[10];
    const float* W1       = (const float*)d_in[11];
    const float* b1       = (const float*)d_in[12];
    const float* W2       = (const float*)d_in[13];
    const float* b2       = (const float*)d_in[14];
    const float* W3       = (const float*)d_in[15];
    const float* b3       = (const float*)d_in[16];
    const float* gamma    = (const float*)d_in[17];
    const float* beta     = (const float*)d_in[18];
    float* out = (float*)d_out;

    int N = in_sizes[0] / FIN;
    int E = in_sizes[1] / 2;

    // 0. detect edge dtype (int64 vs int32 materialization)
    detect_kernel<<<1, 1>>>(ei, E, N);
    // 1. zero deg + BN sums
    init_kernel<<<(N + 255) / 256, 256>>>(N);
    // 2. pack [W_gat | W_gcn | W_sage_r]
    pack_w_kernel<<<(FIN * HH + 255) / 256, 256>>>(W_gat, W_gcn, W_sage_r);
    // 3. XW = x @ Wpack  (N x 384)
    launch_gemm(TAG_EXT, x, FIN, TAG_WPACK, nullptr, C3, TAG_XW, nullptr, C3,
                N, FIN, C3, nullptr, TAG_EXT, 0, TAG_EXT, TAG_EXT, 0);
    // 4. degree count over original edges
    count_deg_kernel<<<(E + 255) / 256, 256>>>(ei, E, N);
    // 5. scan -> rowptr/cursor + dinv
    scan_kernel<<<1, 1024>>>(N);
    // 6. per-node attention scalars
    asad_kernel<<<(N * 32 + 255) / 256, 256>>>(att_src, att_dst, N);
    // 7. CSR bucket fill
    scatter_kernel<<<(E + 255) / 256, 256>>>(ei, E, N);
    // 8. fused GAT/GCN/SAGE aggregation
    gather_kernel<<<(N * 32 + 255) / 256, 256>>>(x, b_gat, b_gcn, N);
    // 9. h[:,256:384] = meanb @ W_sage_l + b_sage_l + XW[:,256:384]
    launch_gemm(TAG_MEANB, nullptr, HH, TAG_EXT, W_sage_l, HH, TAG_H256, nullptr, C3,
                N, HH, HH, b_sage_l, TAG_XW256, C3, TAG_EXT, TAG_EXT, 0);
    // 10. batch-norm statistics + fold
    bn_stats_kernel<<<1024, C3>>>(N);
    bn_final_kernel<<<1, C3>>>(gamma, beta, N);
    // 11. MLP1: z1 = relu(bn(h)) @ W1 + b1
    launch_gemm(TAG_H, nullptr, C3, TAG_EXT, W1, 256, TAG_Z1, nullptr, 256,
                N, C3, 256, b1, TAG_EXT, 0, TAG_BNS, TAG_BNT, 1);
    // 12. MLP2: z2 = relu(z1) @ W2 + b2
    launch_gemm(TAG_Z1, nullptr, 256, TAG_EXT, W2, 128, TAG_Z2, nullptr, 128,
                N, 256, 128, b2, TAG_EXT, 0, TAG_EXT, TAG_EXT, 1);
    // 13. MLP3: out = relu(z2) @ W3 + b3
    launch_gemm(TAG_Z2, nullptr, 128, TAG_EXT, W3, 40, TAG_EXT, out, 40,
                N, 128, 40, b3, TAG_EXT, 0, TAG_EXT, TAG_EXT, 1);
}

// round 4
// speedup vs baseline: 2.2910x; 2.2910x over previous
#include <cuda_runtime.h>
#include <cstdint>

#define FIN 128
#define HH  128
#define C3  384
#define MAXN 50000
#define MAXE 800000
#define BM 128
#define BN 128
#define BKT 32

// ---------------- static device scratch (allocation-free rule) ----------------
__device__ float d_XW[(size_t)MAXN * C3];     // [hgat | hgcn | x@W_sage_r]
__device__ float d_h[(size_t)MAXN * C3];      // concat features
__device__ float d_meanb[(size_t)MAXN * HH];  // SAGE neighbor mean
__device__ float d_z1[(size_t)MAXN * 256];
__device__ float d_z2[(size_t)MAXN * 128];
__device__ float d_as[MAXN], d_ad[MAXN], d_dinv[MAXN];
__device__ int   d_deg[MAXN];
__device__ int   d_rowptr[MAXN + 1];
__device__ int   d_cursor[MAXN];
__device__ int   d_srclist[MAXE];
__device__ float d_Wpack[FIN * C3];
__device__ float d_sum[C3], d_sumsq[C3], d_bns[C3], d_bnt[C3];
__device__ int   d_is32;

// Tags for resolving internal scratch pointers inside device code
#define TAG_EXT     (-1)
#define TAG_XW      0
#define TAG_XW256   1
#define TAG_H       2
#define TAG_H256    3
#define TAG_MEANB   4
#define TAG_Z1      5
#define TAG_Z2      6
#define TAG_WPACK   7
#define TAG_BNS     8
#define TAG_BNT     9

__device__ __forceinline__ const float* resolve_c(int tag, const float* ext) {
    switch (tag) {
        case TAG_XW:    return d_XW;
        case TAG_XW256: return d_XW + 256;
        case TAG_H:     return d_h;
        case TAG_H256:  return d_h + 256;
        case TAG_MEANB: return d_meanb;
        case TAG_Z1:    return d_z1;
        case TAG_Z2:    return d_z2;
        case TAG_WPACK: return d_Wpack;
        case TAG_BNS:   return d_bns;
        case TAG_BNT:   return d_bnt;
        default:        return ext;
    }
}
__device__ __forceinline__ float* resolve_m(int tag, float* ext) {
    switch (tag) {
        case TAG_XW:    return d_XW;
        case TAG_XW256: return d_XW + 256;
        case TAG_H:     return d_h;
        case TAG_H256:  return d_h + 256;
        case TAG_MEANB: return d_meanb;
        case TAG_Z1:    return d_z1;
        case TAG_Z2:    return d_z2;
        default:        return ext;
    }
}

// ---------------- edge dtype detection + safe accessor ----------------
__global__ void detect_kernel(const void* ei, int E, int n) {
    const long long* p64 = (const long long*)ei;
    int ok64 = 1;
    for (int i = 0; i < 16; i++) {
        size_t idx = ((size_t)i * 2654435761u) % (size_t)E;
        long long v = p64[idx];
        if (v < 0 || v >= (long long)n) { ok64 = 0; break; }
    }
    d_is32 = ok64 ? 0 : 1;
}

__device__ __forceinline__ int edge_get(const void* ei, size_t i, int n) {
    long long v = d_is32 ? (long long)((const int*)ei)[i]
                         : ((const long long*)ei)[i];
    if (v < 0) v = 0;
    if (v >= n) v = n - 1;
    return (int)v;
}

// ---------------- small kernels ----------------
__global__ void init_kernel(int n) {
    int i = blockIdx.x * blockDim.x + threadIdx.x;
    if (i < n) d_deg[i] = 0;
    if (i < C3) { d_sum[i] = 0.f; d_sumsq[i] = 0.f; }
}

__global__ void pack_w_kernel(const float* __restrict__ Wg,
                              const float* __restrict__ Wc,
                              const float* __restrict__ Wr) {
    int i = blockIdx.x * blockDim.x + threadIdx.x;
    if (i < FIN * HH) {
        int k = i >> 7, j = i & 127;
        d_Wpack[k * C3 + j]       = Wg[i];
        d_Wpack[k * C3 + 128 + j] = Wc[i];
        d_Wpack[k * C3 + 256 + j] = Wr[i];
    }
}

__global__ void count_deg_kernel(const void* __restrict__ ei, int E, int n) {
    int e = blockIdx.x * blockDim.x + threadIdx.x;
    if (e < E) atomicAdd(&d_deg[edge_get(ei, (size_t)E + e, n)], 1);
}

__global__ void scan_kernel(int n) {
    __shared__ int sh[1024];
    int t = threadIdx.x;
    int chunk = (n + 1023) >> 10;
    int st = t * chunk, en = min(st + chunk, n);
    int s = 0;
    for (int i = st; i < en; i++) s += d_deg[i];
    sh[t] = s;
    __syncthreads();
    for (int off = 1; off < 1024; off <<= 1) {
        int add = (t >= off) ? sh[t - off] : 0;
        __syncthreads();
        sh[t] += add;
        __syncthreads();
    }
    int run = (t == 0) ? 0 : sh[t - 1];
    for (int i = st; i < en; i++) {
        d_rowptr[i] = run;
        d_cursor[i] = run;
        d_dinv[i] = rsqrtf((float)d_deg[i] + 1.0f);
        run += d_deg[i];
    }
    if (t == 0) d_rowptr[n] = sh[1023];
}

__global__ void scatter_kernel(const void* __restrict__ ei, int E, int n) {
    int e = blockIdx.x * blockDim.x + threadIdx.x;
    if (e < E) {
        int s = edge_get(ei, (size_t)e, n);
        int d = edge_get(ei, (size_t)E + e, n);
        int pos = atomicAdd(&d_cursor[d], 1);
        if (pos >= 0 && pos < MAXE) d_srclist[pos] = s;
    }
}

__global__ void asad_kernel(const float* __restrict__ att_src,
                            const float* __restrict__ att_dst, int n) {
    int w = (blockIdx.x * blockDim.x + threadIdx.x) >> 5;
    int lane = threadIdx.x & 31;
    if (w >= n) return;
    float4 h4 = ((const float4*)(d_XW + (size_t)w * C3))[lane];
    float4 s4 = ((const float4*)att_src)[lane];
    float4 t4 = ((const float4*)att_dst)[lane];
    float ss = h4.x * s4.x + h4.y * s4.y + h4.z * s4.z + h4.w * s4.w;
    float sd = h4.x * t4.x + h4.y * t4.y + h4.z * t4.z + h4.w * t4.w;
    #pragma unroll
    for (int off = 16; off > 0; off >>= 1) {
        ss += __shfl_down_sync(0xffffffffu, ss, off);
        sd += __shfl_down_sync(0xffffffffu, sd, off);
    }
    if (lane == 0) { d_as[w] = ss; d_ad[w] = sd; }
}

__device__ __forceinline__ float lrelu02(float e) { return e > 0.f ? e : 0.2f * e; }

__global__ void gather_kernel(const float* __restrict__ x,
                              const float* __restrict__ b_gat,
                              const float* __restrict__ b_gcn, int n) {
    int node = (blockIdx.x * blockDim.x + threadIdx.x) >> 5;
    int lane = threadIdx.x & 31;
    if (node >= n) return;
    int beg = d_rowptr[node], end = d_rowptr[node + 1];
    float adi = d_ad[node];
    float dvi = d_dinv[node];

    float4 gat = make_float4(0, 0, 0, 0);
    float4 gcn = make_float4(0, 0, 0, 0);
    float4 sg  = make_float4(0, 0, 0, 0);
    float den = 0.f;

    {
        float w = __expf(lrelu02(d_as[node] + adi));
        den += w;
        const float4* base = (const float4*)(d_XW + (size_t)node * C3);
        float4 hg = base[lane];
        float4 hc = base[32 + lane];
        float nn = dvi * dvi;
        gat.x += w * hg.x; gat.y += w * hg.y; gat.z += w * hg.z; gat.w += w * hg.w;
        gcn.x += nn * hc.x; gcn.y += nn * hc.y; gcn.z += nn * hc.z; gcn.w += nn * hc.w;
    }

    for (int j0 = beg; j0 < end; j0 += 32) {
        int myj = j0 + lane;
        int s = 0; float w = 0.f, nrm = 0.f;
        if (myj < end) {
            s = d_srclist[myj];
            w = __expf(lrelu02(d_as[s] + adi));
            nrm = d_dinv[s] * dvi;
        }
        int cnt = min(32, end - j0);
        for (int q = 0; q < cnt; q++) {
            int   ss = __shfl_sync(0xffffffffu, s, q);
            float wq = __shfl_sync(0xffffffffu, w, q);
            float nq = __shfl_sync(0xffffffffu, nrm, q);
            const float4* base = (const float4*)(d_XW + (size_t)ss * C3);
            float4 hg = base[lane];
            float4 hc = base[32 + lane];
            float4 xv = ((const float4*)(x + (size_t)ss * FIN))[lane];
            gat.x += wq * hg.x; gat.y += wq * hg.y; gat.z += wq * hg.z; gat.w += wq * hg.w;
            gcn.x += nq * hc.x; gcn.y += nq * hc.y; gcn.z += nq * hc.z; gcn.w += nq * hc.w;
            sg.x += xv.x; sg.y += xv.y; sg.z += xv.z; sg.w += xv.w;
            den += wq;
        }
    }

    float invden = 1.0f / den;
    float invcnt = 1.0f / fmaxf((float)(end - beg), 1.0f);
    float4 bg = ((const float4*)b_gat)[lane];
    float4 bc = ((const float4*)b_gcn)[lane];
    float4 og = make_float4(gat.x * invden + bg.x, gat.y * invden + bg.y,
                            gat.z * invden + bg.z, gat.w * invden + bg.w);
    float4 oc = make_float4(gcn.x + bc.x, gcn.y + bc.y, gcn.z + bc.z, gcn.w + bc.w);
    float4 om = make_float4(sg.x * invcnt, sg.y * invcnt, sg.z * invcnt, sg.w * invcnt);
    ((float4*)(d_h + (size_t)node * C3))[lane] = og;
    ((float4*)(d_h + (size_t)node * C3 + 128))[lane] = oc;
    ((float4*)(d_meanb + (size_t)node * HH))[lane] = om;
}

__global__ void bn_stats_kernel(int n) {
    int c = threadIdx.x;
    float s = 0.f, s2 = 0.f;
    for (int r = blockIdx.x; r < n; r += gridDim.x) {
        float v = d_h[(size_t)r * C3 + c];
        s += v; s2 += v * v;
    }
    atomicAdd(&d_sum[c], s);
    atomicAdd(&d_sumsq[c], s2);
}

__global__ void bn_final_kernel(const float* __restrict__ gamma,
                                const float* __restrict__ beta, int n) {
    int c = threadIdx.x;
    if (c < C3) {
        float invn = 1.0f / (float)n;
        float mu = d_sum[c] * invn;
        float var = d_sumsq[c] * invn - mu * mu;
        float r = rsqrtf(var + 1e-5f);
        d_bns[c] = r * gamma[c];
        d_bnt[c] = beta[c] - mu * r * gamma[c];
    }
}

// ---------------- TF32 tensor-core GEMM ----------------
// C = op(A) @ B [+bias] [+addv];  op(A) = optional per-K affine + relu.
// BM=128, BN=128, BK=32; 8 warps (4x2), warp tile 32x64 via m16n8k8.
__device__ __forceinline__ uint32_t f2tf32(float f) {
    uint32_t o; asm("cvt.rna.tf32.f32 %0, %1;" : "=r"(o) : "f"(f)); return o;
}
__device__ __forceinline__ void mma_tf32(float* c, const uint32_t* a, const uint32_t* b) {
    asm volatile(
        "mma.sync.aligned.m16n8k8.row.col.f32.tf32.tf32.f32 "
        "{%0,%1,%2,%3}, {%4,%5,%6,%7}, {%8,%9}, {%0,%1,%2,%3};"
        : "+f"(c[0]), "+f"(c[1]), "+f"(c[2]), "+f"(c[3])
        : "r"(a[0]), "r"(a[1]), "r"(a[2]), "r"(a[3]), "r"(b[0]), "r"(b[1]));
}

__global__ void __launch_bounds__(256)
gemm_tc_kernel(int aTag, const float* aExt, int lda,
               int bTag, const float* bExt, int ldb,
               int cTag, float* cExt, int ldc,
               int M, int K, int Ncol,
               const float* __restrict__ bias,
               int addTag, int ldadd,
               int scaleTag, int shiftTag, int reluA) {
    const float* __restrict__ A = resolve_c(aTag, aExt);
    const float* __restrict__ B = resolve_c(bTag, bExt);
    float* __restrict__ C = resolve_m(cTag, cExt);
    const float* __restrict__ addv   = (addTag   == TAG_EXT) ? nullptr : resolve_c(addTag, nullptr);
    const float* __restrict__ ascale = (scaleTag == TAG_EXT) ? nullptr : resolve_c(scaleTag, nullptr);
    const float* __restrict__ ashift = (shiftTag == TAG_EXT) ? nullptr : resolve_c(shiftTag, nullptr);

    __shared__ float As[BM][BKT + 4];   // m-major, padded (stride 36)
    __shared__ float Bs[BKT][BN + 4];   // k-major, padded (stride 132)

    int tid  = threadIdx.x;
    int warp = tid >> 5, lane = tid & 31;
    int wm = warp & 3, wn = warp >> 2;        // 4x2 warps
    int gid = lane >> 2, tig = lane & 3;
    int row0 = blockIdx.y * BM, col0 = blockIdx.x * BN;

    float acc[2][8][4];
    #pragma unroll
    for (int mt = 0; mt < 2; mt++)
        #pragma unroll
        for (int nt = 0; nt < 8; nt++)
            #pragma unroll
            for (int r = 0; r < 4; r++) acc[mt][nt][r] = 0.f;

    // A-load coords: 4 float4/thread (rows (tid>>3)+32i, cols (tid&7)*4)
    int a_m  = tid >> 3;
    int a_k4 = (tid & 7) * 4;

    for (int k0 = 0; k0 < K; k0 += BKT) {
        #pragma unroll
        for (int i = 0; i < 4; i++) {
            int m = a_m + 32 * i;
            int gm = row0 + m;
            float4 v = make_float4(0.f, 0.f, 0.f, 0.f);
            if (gm < M) v = *(const float4*)(A + (size_t)gm * lda + k0 + a_k4);
            if (ascale) {
                int gk = k0 + a_k4;
                v.x = v.x * ascale[gk + 0] + ashift[gk + 0];
                v.y = v.y * ascale[gk + 1] + ashift[gk + 1];
                v.z = v.z * ascale[gk + 2] + ashift[gk + 2];
                v.w = v.w * ascale[gk + 3] + ashift[gk + 3];
            }
            if (reluA) {
                v.x = fmaxf(v.x, 0.f); v.y = fmaxf(v.y, 0.f);
                v.z = fmaxf(v.z, 0.f); v.w = fmaxf(v.w, 0.f);
            }
            As[m][a_k4 + 0] = __uint_as_float(f2tf32(v.x));
            As[m][a_k4 + 1] = __uint_as_float(f2tf32(v.y));
            As[m][a_k4 + 2] = __uint_as_float(f2tf32(v.z));
            As[m][a_k4 + 3] = __uint_as_float(f2tf32(v.w));
        }
        #pragma unroll
        for (int i = 0; i < 4; i++) {
            int idx = tid + 256 * i;
            int k = idx >> 5;
            int nc = (idx & 31) * 4;
            float4 v = make_float4(0.f, 0.f, 0.f, 0.f);
            if (col0 + nc < Ncol)
                v = *(const float4*)(B + (size_t)(k0 + k) * ldb + col0 + nc);
            Bs[k][nc + 0] = __uint_as_float(f2tf32(v.x));
            Bs[k][nc + 1] = __uint_as_float(f2tf32(v.y));
            Bs[k][nc + 2] = __uint_as_float(f2tf32(v.z));
            Bs[k][nc + 3] = __uint_as_float(f2tf32(v.w));
        }
        __syncthreads();

        #pragma unroll
        for (int ks = 0; ks < BKT; ks += 8) {
            uint32_t af[2][4];
            #pragma unroll
            for (int mt = 0; mt < 2; mt++) {
                int m = wm * 32 + mt * 16;
                af[mt][0] = __float_as_uint(As[m + gid    ][ks + tig    ]);
                af[mt][1] = __float_as_uint(As[m + gid + 8][ks + tig    ]);
                af[mt][2] = __float_as_uint(As[m + gid    ][ks + tig + 4]);
                af[mt][3] = __float_as_uint(As[m + gid + 8][ks + tig + 4]);
            }
            uint32_t bf[8][2];
            #pragma unroll
            for (int nt = 0; nt < 8; nt++) {
                int nn = wn * 64 + nt * 8 + gid;
                bf[nt][0] = __float_as_uint(Bs[ks + tig    ][nn]);
                bf[nt][1] = __float_as_uint(Bs[ks + tig + 4][nn]);
            }
            #pragma unroll
            for (int mt = 0; mt < 2; mt++)
                #pragma unroll
                for (int nt = 0; nt < 8; nt++)
                    mma_tf32(acc[mt][nt], af[mt], bf[nt]);
        }
        __syncthreads();
    }

    // epilogue
    #pragma unroll
    for (int mt = 0; mt < 2; mt++) {
        #pragma unroll
        for (int nt = 0; nt < 8; nt++) {
            int n0 = col0 + wn * 64 + nt * 8 + 2 * tig;
            if (n0 >= Ncol) continue;
            float b0 = bias ? bias[n0] : 0.f;
            float b1 = bias ? bias[n0 + 1] : 0.f;
            #pragma unroll
            for (int half = 0; half < 2; half++) {
                int r = row0 + wm * 32 + mt * 16 + gid + half * 8;
                if (r >= M) continue;
                float v0 = acc[mt][nt][half * 2 + 0] + b0;
                float v1 = acc[mt][nt][half * 2 + 1] + b1;
                if (addv) {
                    v0 += addv[(size_t)r * ldadd + n0];
                    v1 += addv[(size_t)r * ldadd + n0 + 1];
                }
                float2 o = make_float2(v0, v1);
                *(float2*)(C + (size_t)r * ldc + n0) = o;
            }
        }
    }
}

static void launch_gemm(int aTag, const float* aExt, int lda,
                        int bTag, const float* bExt, int ldb,
                        int cTag, float* cExt, int ldc,
                        int M, int K, int Ncol,
                        const float* bias,
                        int addTag, int ldadd,
                        int scaleTag, int shiftTag, int reluA) {
    dim3 g((Ncol + BN - 1) / BN, (M + BM - 1) / BM);
    gemm_tc_kernel<<<g, 256>>>(aTag, aExt, lda, bTag, bExt, ldb, cTag, cExt, ldc,
                               M, K, Ncol, bias, addTag, ldadd,
                               scaleTag, shiftTag, reluA);
}

// ---------------- launch ----------------
extern "C" void kernel_launch(void* const* d_in, const int* in_sizes, int n_in,
                              void* d_out, int out_size) {
    const float* x        = (const float*)d_in[0];
    const void*  ei       = d_in[1];
    const float* W_gat    = (const float*)d_in[2];
    const float* att_src  = (const float*)d_in[3];
    const float* att_dst  = (const float*)d_in[4];
    const float* b_gat    = (const float*)d_in[5];
    const float* W_gcn    = (const float*)d_in[6];
    const float* b_gcn    = (const float*)d_in[7];
    const float* W_sage_l = (const float*)d_in[8];
    const float* b_sage_l = (const float*)d_in[9];
    const float* W_sage_r = (const float*)d_in[10];
    const float* W1       = (const float*)d_in[11];
    const float* b1       = (const float*)d_in[12];
    const float* W2       = (const float*)d_in[13];
    const float* b2       = (const float*)d_in[14];
    const float* W3       = (const float*)d_in[15];
    const float* b3       = (const float*)d_in[16];
    const float* gamma    = (const float*)d_in[17];
    const float* beta     = (const float*)d_in[18];
    float* out = (float*)d_out;

    int N = in_sizes[0] / FIN;
    int E = in_sizes[1] / 2;

    detect_kernel<<<1, 1>>>(ei, E, N);
    init_kernel<<<(N + 255) / 256, 256>>>(N);
    pack_w_kernel<<<(FIN * HH + 255) / 256, 256>>>(W_gat, W_gcn, W_sage_r);
    // XW = x @ Wpack  (N x 384)
    launch_gemm(TAG_EXT, x, FIN, TAG_WPACK, nullptr, C3, TAG_XW, nullptr, C3,
                N, FIN, C3, nullptr, TAG_EXT, 0, TAG_EXT, TAG_EXT, 0);
    count_deg_kernel<<<(E + 255) / 256, 256>>>(ei, E, N);
    scan_kernel<<<1, 1024>>>(N);
    asad_kernel<<<(N * 32 + 255) / 256, 256>>>(att_src, att_dst, N);
    scatter_kernel<<<(E + 255) / 256, 256>>>(ei, E, N);
    gather_kernel<<<(N * 32 + 255) / 256, 256>>>(x, b_gat, b_gcn, N);
    // h[:,256:384] = meanb @ W_sage_l + b_sage_l + XW[:,256:384]
    launch_gemm(TAG_MEANB, nullptr, HH, TAG_EXT, W_sage_l, HH, TAG_H256, nullptr, C3,
                N, HH, HH, b_sage_l, TAG_XW256, C3, TAG_EXT, TAG_EXT, 0);
    bn_stats_kernel<<<1024, C3>>>(N);
    bn_final_kernel<<<1, C3>>>(gamma, beta, N);
    // MLP1: z1 = relu(bn(h)) @ W1 + b1
    launch_gemm(TAG_H, nullptr, C3, TAG_EXT, W1, 256, TAG_Z1, nullptr, 256,
                N, C3, 256, b1, TAG_EXT, 0, TAG_BNS, TAG_BNT, 1);
    // MLP2: z2 = relu(z1) @ W2 + b2
    launch_gemm(TAG_Z1, nullptr, 256, TAG_EXT, W2, 128, TAG_Z2, nullptr, 128,
                N, 256, 128, b2, TAG_EXT, 0, TAG_EXT, TAG_EXT, 1);
    // MLP3: out = relu(z2) @ W3 + b3
    launch_gemm(TAG_Z2, nullptr, 128, TAG_EXT, W3, 40, TAG_EXT, out, 40,
                N, 128, 40, b3, TAG_EXT, 0, TAG_EXT, TAG_EXT, 1);
}

// round 5
// speedup vs baseline: 2.3405x; 1.0216x over previous
#include <cuda_runtime.h>
#include <cstdint>

#define FIN 128
#define HH  128
#define C3  384
#define MAXN 50000
#define MAXE 800000
#define BM 128
#define BN 128
#define BKT 32

// ---------------- static device scratch (allocation-free rule) ----------------
__device__ float d_scr[(size_t)MAXN * C3];    // [aggG | aggC | xr] (N*128 each)
__device__ float d_h[(size_t)MAXN * C3];      // concat features
__device__ float d_meanb[(size_t)MAXN * HH];  // SAGE neighbor mean
__device__ float d_z1[(size_t)MAXN * 256];
__device__ float d_z2[(size_t)MAXN * 128];
__device__ float d_as[MAXN], d_ad[MAXN], d_dinv[MAXN];
__device__ int   d_deg[MAXN];
__device__ int   d_rowptr[MAXN + 1];
__device__ int   d_cursor[MAXN];
__device__ int   d_srclist[MAXE];
__device__ float d_was[FIN], d_wad[FIN];
__device__ float d_sum[C3], d_sumsq[C3], d_bns[C3], d_bnt[C3];
__device__ int   d_is32;

// Tags for resolving internal scratch pointers inside device code
#define TAG_EXT   (-1)
#define TAG_AGGG  0
#define TAG_AGGC  1
#define TAG_XR    2
#define TAG_H     3
#define TAG_H128  4
#define TAG_H256  5
#define TAG_MEANB 6
#define TAG_Z1    7
#define TAG_Z2    8
#define TAG_BNS   9
#define TAG_BNT   10

__device__ __forceinline__ const float* resolve_c(int tag, const float* ext) {
    switch (tag) {
        case TAG_AGGG:  return d_scr;
        case TAG_AGGC:  return d_scr + (size_t)MAXN * 128;
        case TAG_XR:    return d_scr + (size_t)2 * MAXN * 128;
        case TAG_H:     return d_h;
        case TAG_H128:  return d_h + 128;
        case TAG_H256:  return d_h + 256;
        case TAG_MEANB: return d_meanb;
        case TAG_Z1:    return d_z1;
        case TAG_Z2:    return d_z2;
        case TAG_BNS:   return d_bns;
        case TAG_BNT:   return d_bnt;
        default:        return ext;
    }
}
__device__ __forceinline__ float* resolve_m(int tag, float* ext) {
    switch (tag) {
        case TAG_AGGG:  return d_scr;
        case TAG_AGGC:  return d_scr + (size_t)MAXN * 128;
        case TAG_XR:    return d_scr + (size_t)2 * MAXN * 128;
        case TAG_H:     return d_h;
        case TAG_H128:  return d_h + 128;
        case TAG_H256:  return d_h + 256;
        case TAG_MEANB: return d_meanb;
        case TAG_Z1:    return d_z1;
        case TAG_Z2:    return d_z2;
        default:        return ext;
    }
}

// ---------------- edge dtype detection + safe accessor ----------------
__global__ void detect_kernel(const void* ei, int E, int n) {
    const long long* p64 = (const long long*)ei;
    int ok64 = 1;
    for (int i = 0; i < 16; i++) {
        size_t idx = ((size_t)i * 2654435761u) % (size_t)E;
        long long v = p64[idx];
        if (v < 0 || v >= (long long)n) { ok64 = 0; break; }
    }
    d_is32 = ok64 ? 0 : 1;
}

__device__ __forceinline__ int edge_get(const void* ei, size_t i, int n) {
    long long v = d_is32 ? (long long)((const int*)ei)[i]
                         : ((const long long*)ei)[i];
    if (v < 0) v = 0;
    if (v >= n) v = n - 1;
    return (int)v;
}

// ---------------- small kernels ----------------
__global__ void init_kernel(int n) {
    int i = blockIdx.x * blockDim.x + threadIdx.x;
    if (i < n) d_deg[i] = 0;
    if (i < C3) { d_sum[i] = 0.f; d_sumsq[i] = 0.f; }
}

// w_as = W_gat @ att_src, w_ad = W_gat @ att_dst   (128 threads)
__global__ void watt_kernel(const float* __restrict__ Wg,
                            const float* __restrict__ att_s,
                            const float* __restrict__ att_d) {
    int k = threadIdx.x;
    float s1 = 0.f, s2 = 0.f;
    #pragma unroll
    for (int j = 0; j < FIN; j += 4) {
        float4 w = *(const float4*)(Wg + k * FIN + j);
        float4 a = *(const float4*)(att_s + j);
        float4 b = *(const float4*)(att_d + j);
        s1 += w.x * a.x + w.y * a.y + w.z * a.z + w.w * a.w;
        s2 += w.x * b.x + w.y * b.y + w.z * b.z + w.w * b.w;
    }
    d_was[k] = s1;
    d_wad[k] = s2;
}

// a_s[i] = x[i]·w_as, a_d[i] = x[i]·w_ad ; one warp per node
__global__ void asad_kernel(const float* __restrict__ x, int n) {
    int w = (blockIdx.x * blockDim.x + threadIdx.x) >> 5;
    int lane = threadIdx.x & 31;
    if (w >= n) return;
    float4 h4 = ((const float4*)(x + (size_t)w * FIN))[lane];
    float4 s4 = ((const float4*)d_was)[lane];
    float4 t4 = ((const float4*)d_wad)[lane];
    float ss = h4.x * s4.x + h4.y * s4.y + h4.z * s4.z + h4.w * s4.w;
    float sd = h4.x * t4.x + h4.y * t4.y + h4.z * t4.z + h4.w * t4.w;
    #pragma unroll
    for (int off = 16; off > 0; off >>= 1) {
        ss += __shfl_down_sync(0xffffffffu, ss, off);
        sd += __shfl_down_sync(0xffffffffu, sd, off);
    }
    if (lane == 0) { d_as[w] = ss; d_ad[w] = sd; }
}

__global__ void count_deg_kernel(const void* __restrict__ ei, int E, int n) {
    int e = blockIdx.x * blockDim.x + threadIdx.x;
    if (e < E) atomicAdd(&d_deg[edge_get(ei, (size_t)E + e, n)], 1);
}

__global__ void scan_kernel(int n) {
    __shared__ int sh[1024];
    int t = threadIdx.x;
    int chunk = (n + 1023) >> 10;
    int st = t * chunk, en = min(st + chunk, n);
    int s = 0;
    for (int i = st; i < en; i++) s += d_deg[i];
    sh[t] = s;
    __syncthreads();
    for (int off = 1; off < 1024; off <<= 1) {
        int add = (t >= off) ? sh[t - off] : 0;
        __syncthreads();
        sh[t] += add;
        __syncthreads();
    }
    int run = (t == 0) ? 0 : sh[t - 1];
    for (int i = st; i < en; i++) {
        d_rowptr[i] = run;
        d_cursor[i] = run;
        d_dinv[i] = rsqrtf((float)d_deg[i] + 1.0f);
        run += d_deg[i];
    }
    if (t == 0) d_rowptr[n] = sh[1023];
}

__global__ void scatter_kernel(const void* __restrict__ ei, int E, int n) {
    int e = blockIdx.x * blockDim.x + threadIdx.x;
    if (e < E) {
        int s = edge_get(ei, (size_t)e, n);
        int d = edge_get(ei, (size_t)E + e, n);
        int pos = atomicAdd(&d_cursor[d], 1);
        if (pos >= 0 && pos < MAXE) d_srclist[pos] = s;
    }
}

__device__ __forceinline__ float lrelu02(float e) { return e > 0.f ? e : 0.2f * e; }

// warp per dst node: fused x-space aggregation for GAT + GCN + SAGE.
// Single x[src] row load feeds all three accumulators.
__global__ void gather_kernel(const float* __restrict__ x, int n) {
    int node = (blockIdx.x * blockDim.x + threadIdx.x) >> 5;
    int lane = threadIdx.x & 31;
    if (node >= n) return;
    int beg = d_rowptr[node], end = d_rowptr[node + 1];
    float adi = d_ad[node];
    float dvi = d_dinv[node];

    float4 gat, gcn;
    float4 sg = make_float4(0, 0, 0, 0);
    float den;

    // self loop (GAT + GCN)
    {
        float w = __expf(lrelu02(d_as[node] + adi));
        den = w;
        float nn = dvi * dvi;
        float4 xv = ((const float4*)(x + (size_t)node * FIN))[lane];
        gat = make_float4(w * xv.x, w * xv.y, w * xv.z, w * xv.w);
        gcn = make_float4(nn * xv.x, nn * xv.y, nn * xv.z, nn * xv.w);
    }

    for (int j0 = beg; j0 < end; j0 += 32) {
        int myj = j0 + lane;
        int s = 0; float w = 0.f, nrm = 0.f;
        if (myj < end) {
            s = d_srclist[myj];
            w = __expf(lrelu02(d_as[s] + adi));
            nrm = d_dinv[s] * dvi;
        }
        int cnt = min(32, end - j0);
        for (int q = 0; q < cnt; q++) {
            int   ss = __shfl_sync(0xffffffffu, s, q);
            float wq = __shfl_sync(0xffffffffu, w, q);
            float nq = __shfl_sync(0xffffffffu, nrm, q);
            float4 xv = ((const float4*)(x + (size_t)ss * FIN))[lane];
            gat.x += wq * xv.x; gat.y += wq * xv.y; gat.z += wq * xv.z; gat.w += wq * xv.w;
            gcn.x += nq * xv.x; gcn.y += nq * xv.y; gcn.z += nq * xv.z; gcn.w += nq * xv.w;
            sg.x += xv.x; sg.y += xv.y; sg.z += xv.z; sg.w += xv.w;
            den += wq;
        }
    }

    float invden = 1.0f / den;
    float invcnt = 1.0f / fmaxf((float)(end - beg), 1.0f);
    float4 og = make_float4(gat.x * invden, gat.y * invden,
                            gat.z * invden, gat.w * invden);
    float4 om = make_float4(sg.x * invcnt, sg.y * invcnt,
                            sg.z * invcnt, sg.w * invcnt);
    ((float4*)(d_scr + (size_t)node * 128))[lane] = og;                       // aggG
    ((float4*)(d_scr + (size_t)MAXN * 128 + (size_t)node * 128))[lane] = gcn; // aggC
    ((float4*)(d_meanb + (size_t)node * HH))[lane] = om;
}

__global__ void bn_stats_kernel(int n) {
    int c = threadIdx.x;
    float s = 0.f, s2 = 0.f;
    for (int r = blockIdx.x; r < n; r += gridDim.x) {
        float v = d_h[(size_t)r * C3 + c];
        s += v; s2 += v * v;
    }
    atomicAdd(&d_sum[c], s);
    atomicAdd(&d_sumsq[c], s2);
}

__global__ void bn_final_kernel(const float* __restrict__ gamma,
                                const float* __restrict__ beta, int n) {
    int c = threadIdx.x;
    if (c < C3) {
        float invn = 1.0f / (float)n;
        float mu = d_sum[c] * invn;
        float var = d_sumsq[c] * invn - mu * mu;
        float r = rsqrtf(var + 1e-5f);
        d_bns[c] = r * gamma[c];
        d_bnt[c] = beta[c] - mu * r * gamma[c];
    }
}

// ---------------- TF32 tensor-core GEMM ----------------
__device__ __forceinline__ uint32_t f2tf32(float f) {
    uint32_t o; asm("cvt.rna.tf32.f32 %0, %1;" : "=r"(o) : "f"(f)); return o;
}
__device__ __forceinline__ void mma_tf32(float* c, const uint32_t* a, const uint32_t* b) {
    asm volatile(
        "mma.sync.aligned.m16n8k8.row.col.f32.tf32.tf32.f32 "
        "{%0,%1,%2,%3}, {%4,%5,%6,%7}, {%8,%9}, {%0,%1,%2,%3};"
        : "+f"(c[0]), "+f"(c[1]), "+f"(c[2]), "+f"(c[3])
        : "r"(a[0]), "r"(a[1]), "r"(a[2]), "r"(a[3]), "r"(b[0]), "r"(b[1]));
}

__global__ void __launch_bounds__(256)
gemm_tc_kernel(int aTag, const float* aExt, int lda,
               int bTag, const float* bExt, int ldb,
               int cTag, float* cExt, int ldc,
               int M, int K, int Ncol,
               const float* __restrict__ bias,
               int addTag, int ldadd,
               int scaleTag, int shiftTag, int reluA) {
    const float* __restrict__ A = resolve_c(aTag, aExt);
    const float* __restrict__ B = resolve_c(bTag, bExt);
    float* __restrict__ C = resolve_m(cTag, cExt);
    const float* __restrict__ addv   = (addTag   == TAG_EXT) ? nullptr : resolve_c(addTag, nullptr);
    const float* __restrict__ ascale = (scaleTag == TAG_EXT) ? nullptr : resolve_c(scaleTag, nullptr);
    const float* __restrict__ ashift = (shiftTag == TAG_EXT) ? nullptr : resolve_c(shiftTag, nullptr);

    __shared__ float As[BM][BKT + 4];
    __shared__ float Bs[BKT][BN + 4];

    int tid  = threadIdx.x;
    int warp = tid >> 5, lane = tid & 31;
    int wm = warp & 3, wn = warp >> 2;
    int gid = lane >> 2, tig = lane & 3;
    int row0 = blockIdx.y * BM, col0 = blockIdx.x * BN;

    float acc[2][8][4];
    #pragma unroll
    for (int mt = 0; mt < 2; mt++)
        #pragma unroll
        for (int nt = 0; nt < 8; nt++)
            #pragma unroll
            for (int r = 0; r < 4; r++) acc[mt][nt][r] = 0.f;

    int a_m  = tid >> 3;
    int a_k4 = (tid & 7) * 4;

    for (int k0 = 0; k0 < K; k0 += BKT) {
        #pragma unroll
        for (int i = 0; i < 4; i++) {
            int m = a_m + 32 * i;
            int gm = row0 + m;
            float4 v = make_float4(0.f, 0.f, 0.f, 0.f);
            if (gm < M) v = *(const float4*)(A + (size_t)gm * lda + k0 + a_k4);
            if (ascale) {
                int gk = k0 + a_k4;
                v.x = v.x * ascale[gk + 0] + ashift[gk + 0];
                v.y = v.y * ascale[gk + 1] + ashift[gk + 1];
                v.z = v.z * ascale[gk + 2] + ashift[gk + 2];
                v.w = v.w * ascale[gk + 3] + ashift[gk + 3];
            }
            if (reluA) {
                v.x = fmaxf(v.x, 0.f); v.y = fmaxf(v.y, 0.f);
                v.z = fmaxf(v.z, 0.f); v.w = fmaxf(v.w, 0.f);
            }
            As[m][a_k4 + 0] = __uint_as_float(f2tf32(v.x));
            As[m][a_k4 + 1] = __uint_as_float(f2tf32(v.y));
            As[m][a_k4 + 2] = __uint_as_float(f2tf32(v.z));
            As[m][a_k4 + 3] = __uint_as_float(f2tf32(v.w));
        }
        #pragma unroll
        for (int i = 0; i < 4; i++) {
            int idx = tid + 256 * i;
            int k = idx >> 5;
            int nc = (idx & 31) * 4;
            float4 v = make_float4(0.f, 0.f, 0.f, 0.f);
            if (col0 + nc < Ncol)
                v = *(const float4*)(B + (size_t)(k0 + k) * ldb + col0 + nc);
            Bs[k][nc + 0] = __uint_as_float(f2tf32(v.x));
            Bs[k][nc + 1] = __uint_as_float(f2tf32(v.y));
            Bs[k][nc + 2] = __uint_as_float(f2tf32(v.z));
            Bs[k][nc + 3] = __uint_as_float(f2tf32(v.w));
        }
        __syncthreads();

        #pragma unroll
        for (int ks = 0; ks < BKT; ks += 8) {
            uint32_t af[2][4];
            #pragma unroll
            for (int mt = 0; mt < 2; mt++) {
                int m = wm * 32 + mt * 16;
                af[mt][0] = __float_as_uint(As[m + gid    ][ks + tig    ]);
                af[mt][1] = __float_as_uint(As[m + gid + 8][ks + tig    ]);
                af[mt][2] = __float_as_uint(As[m + gid    ][ks + tig + 4]);
                af[mt][3] = __float_as_uint(As[m + gid + 8][ks + tig + 4]);
            }
            uint32_t bf[8][2];
            #pragma unroll
            for (int nt = 0; nt < 8; nt++) {
                int nn = wn * 64 + nt * 8 + gid;
                bf[nt][0] = __float_as_uint(Bs[ks + tig    ][nn]);
                bf[nt][1] = __float_as_uint(Bs[ks + tig + 4][nn]);
            }
            #pragma unroll
            for (int mt = 0; mt < 2; mt++)
                #pragma unroll
                for (int nt = 0; nt < 8; nt++)
                    mma_tf32(acc[mt][nt], af[mt], bf[nt]);
        }
        __syncthreads();
    }

    #pragma unroll
    for (int mt = 0; mt < 2; mt++) {
        #pragma unroll
        for (int nt = 0; nt < 8; nt++) {
            int n0 = col0 + wn * 64 + nt * 8 + 2 * tig;
            if (n0 >= Ncol) continue;
            float b0 = bias ? bias[n0] : 0.f;
            float b1 = bias ? bias[n0 + 1] : 0.f;
            #pragma unroll
            for (int half = 0; half < 2; half++) {
                int r = row0 + wm * 32 + mt * 16 + gid + half * 8;
                if (r >= M) continue;
                float v0 = acc[mt][nt][half * 2 + 0] + b0;
                float v1 = acc[mt][nt][half * 2 + 1] + b1;
                if (addv) {
                    v0 += addv[(size_t)r * ldadd + n0];
                    v1 += addv[(size_t)r * ldadd + n0 + 1];
                }
                float2 o = make_float2(v0, v1);
                *(float2*)(C + (size_t)r * ldc + n0) = o;
            }
        }
    }
}

static void launch_gemm(int aTag, const float* aExt, int lda,
                        int bTag, const float* bExt, int ldb,
                        int cTag, float* cExt, int ldc,
                        int M, int K, int Ncol,
                        const float* bias,
                        int addTag, int ldadd,
                        int scaleTag, int shiftTag, int reluA) {
    dim3 g((Ncol + BN - 1) / BN, (M + BM - 1) / BM);
    gemm_tc_kernel<<<g, 256>>>(aTag, aExt, lda, bTag, bExt, ldb, cTag, cExt, ldc,
                               M, K, Ncol, bias, addTag, ldadd,
                               scaleTag, shiftTag, reluA);
}

// ---------------- launch ----------------
extern "C" void kernel_launch(void* const* d_in, const int* in_sizes, int n_in,
                              void* d_out, int out_size) {
    const float* x        = (const float*)d_in[0];
    const void*  ei       = d_in[1];
    const float* W_gat    = (const float*)d_in[2];
    const float* att_src  = (const float*)d_in[3];
    const float* att_dst  = (const float*)d_in[4];
    const float* b_gat    = (const float*)d_in[5];
    const float* W_gcn    = (const float*)d_in[6];
    const float* b_gcn    = (const float*)d_in[7];
    const float* W_sage_l = (const float*)d_in[8];
    const float* b_sage_l = (const float*)d_in[9];
    const float* W_sage_r = (const float*)d_in[10];
    const float* W1       = (const float*)d_in[11];
    const float* b1       = (const float*)d_in[12];
    const float* W2       = (const float*)d_in[13];
    const float* b2       = (const float*)d_in[14];
    const float* W3       = (const float*)d_in[15];
    const float* b3       = (const float*)d_in[16];
    const float* gamma    = (const float*)d_in[17];
    const float* beta     = (const float*)d_in[18];
    float* out = (float*)d_out;

    int N = in_sizes[0] / FIN;
    int E = in_sizes[1] / 2;

    detect_kernel<<<1, 1>>>(ei, E, N);
    init_kernel<<<(N + 255) / 256, 256>>>(N);
    // attention projection vectors (tiny)
    watt_kernel<<<1, FIN>>>(W_gat, att_src, att_dst);
    // a_s/a_d directly from x
    asad_kernel<<<(N * 32 + 255) / 256, 256>>>(x, N);
    count_deg_kernel<<<(E + 255) / 256, 256>>>(ei, E, N);
    scan_kernel<<<1, 1024>>>(N);
    scatter_kernel<<<(E + 255) / 256, 256>>>(ei, E, N);
    // fused x-space aggregation (1 row load per edge)
    gather_kernel<<<(N * 32 + 255) / 256, 256>>>(x, N);
    // h[:,0:128]   = aggG @ W_gat + b_gat
    launch_gemm(TAG_AGGG, nullptr, 128, TAG_EXT, W_gat, HH, TAG_H, nullptr, C3,
                N, FIN, HH, b_gat, TAG_EXT, 0, TAG_EXT, TAG_EXT, 0);
    // h[:,128:256] = aggC @ W_gcn + b_gcn
    launch_gemm(TAG_AGGC, nullptr, 128, TAG_EXT, W_gcn, HH, TAG_H128, nullptr, C3,
                N, FIN, HH, b_gcn, TAG_EXT, 0, TAG_EXT, TAG_EXT, 0);
    // xr = x @ W_sage_r
    launch_gemm(TAG_EXT, x, FIN, TAG_EXT, W_sage_r, HH, TAG_XR, nullptr, 128,
                N, FIN, HH, nullptr, TAG_EXT, 0, TAG_EXT, TAG_EXT, 0);
    // h[:,256:384] = meanb @ W_sage_l + b_sage_l + xr
    launch_gemm(TAG_MEANB, nullptr, HH, TAG_EXT, W_sage_l, HH, TAG_H256, nullptr, C3,
                N, HH, HH, b_sage_l, TAG_XR, 128, TAG_EXT, TAG_EXT, 0);
    bn_stats_kernel<<<1024, C3>>>(N);
    bn_final_kernel<<<1, C3>>>(gamma, beta, N);
    // MLP1: z1 = relu(bn(h)) @ W1 + b1
    launch_gemm(TAG_H, nullptr, C3, TAG_EXT, W1, 256, TAG_Z1, nullptr, 256,
                N, C3, 256, b1, TAG_EXT, 0, TAG_BNS, TAG_BNT, 1);
    // MLP2: z2 = relu(z1) @ W2 + b2
    launch_gemm(TAG_Z1, nullptr, 256, TAG_EXT, W2, 128, TAG_Z2, nullptr, 128,
                N, 256, 128, b2, TAG_EXT, 0, TAG_EXT, TAG_EXT, 1);
    // MLP3: out = relu(z2) @ W3 + b3
    launch_gemm(TAG_Z2, nullptr, 128, TAG_EXT, W3, 40, TAG_EXT, out, 40,
                N, 128, 40, b3, TAG_EXT, 0, TAG_EXT, TAG_EXT, 1);
}